// round 1
// baseline (speedup 1.0000x reference)
#include <cuda_runtime.h>
#include <math.h>

#define Bsz  64
#define Ssz  256
#define INP  400
#define Hsz  1024
#define H4   4096
#define Gsz  8192
#define NS   150
#define NR   50
#define NBLK 128

// ---------------- scratch (static device allocations are the sanctioned path) ----
static __device__ float    d_Xg[(size_t)Ssz * Gsz * Bsz];   // [s][col(8192)][b]  512MB
static __device__ float    d_Hbuf[2 * Bsz * Hsz];           // [cell][b][j]
static __device__ float    d_T[Bsz * Hsz];                  // recurrent hidden T
static __device__ unsigned g_bar;                           // zero-init
static __device__ unsigned g_gen;                           // zero-init, monotonic

// ---------------- grid barrier (all NBLK blocks resident by construction) -------
__device__ __forceinline__ void gridbar(unsigned& gen) {
    __syncthreads();
    if (threadIdx.x == 0) {
        __threadfence();                       // release producer data
        unsigned arrived = atomicAdd(&g_bar, 1u);
        if (arrived == NBLK - 1) {
            atomicExch(&g_bar, 0u);
            __threadfence();
            atomicAdd(&g_gen, 1u);
        } else {
            while (atomicAdd(&g_gen, 0u) == gen) { /* spin on L2 */ }
        }
        __threadfence();                       // acquire
    }
    __syncthreads();
    gen++;
}

// =================================================================================
// Phase A: Xg[s, col, b] = sum_k x[b,s,k] * Wih_cat[col,k] + (bih+bhh)[col]
// grid = (128 col-tiles, 256 s), 256 threads, 64x64 tile, 4x4 microtile, K chunks 16
// =================================================================================
__global__ void __launch_bounds__(256) phaseA_kernel(
    const float* __restrict__ x,
    const float* __restrict__ WihF, const float* __restrict__ WihR,
    const float* __restrict__ bihF, const float* __restrict__ bhhF,
    const float* __restrict__ bihR, const float* __restrict__ bhhR)
{
    const int s    = blockIdx.y;
    const int col0 = blockIdx.x << 6;
    const int tid  = threadIdx.x;
    const int tx = tid & 15, ty = tid >> 4;
    const int lb = tid >> 2, lk = (tid & 3) << 2;

    __shared__ float xs[16][68];   // [kk][b]
    __shared__ float ws[16][68];   // [kk][c]

    const int colL = col0 + lb;
    const float* wrow = (colL < H4) ? (WihF + (size_t)colL * INP)
                                    : (WihR + (size_t)(colL - H4) * INP);
    const float* xrow = x + ((size_t)lb * Ssz + s) * INP;

    float acc[4][4];
#pragma unroll
    for (int j = 0; j < 4; ++j)
#pragma unroll
        for (int i = 0; i < 4; ++i) acc[j][i] = 0.f;

    float4 tX = *reinterpret_cast<const float4*>(xrow + lk);
    float4 tW = *reinterpret_cast<const float4*>(wrow + lk);

    for (int k0 = 0; k0 < INP; k0 += 16) {
        xs[lk+0][lb] = tX.x; xs[lk+1][lb] = tX.y; xs[lk+2][lb] = tX.z; xs[lk+3][lb] = tX.w;
        ws[lk+0][lb] = tW.x; ws[lk+1][lb] = tW.y; ws[lk+2][lb] = tW.z; ws[lk+3][lb] = tW.w;
        __syncthreads();
        if (k0 + 16 < INP) {
            tX = *reinterpret_cast<const float4*>(xrow + k0 + 16 + lk);
            tW = *reinterpret_cast<const float4*>(wrow + k0 + 16 + lk);
        }
#pragma unroll
        for (int kk = 0; kk < 16; ++kk) {
            float4 bv = *reinterpret_cast<const float4*>(&xs[kk][ty << 2]);
            float4 wv = *reinterpret_cast<const float4*>(&ws[kk][tx << 2]);
            const float bb[4] = {bv.x, bv.y, bv.z, bv.w};
            const float ww[4] = {wv.x, wv.y, wv.z, wv.w};
#pragma unroll
            for (int j = 0; j < 4; ++j)
#pragma unroll
                for (int i = 0; i < 4; ++i) acc[j][i] = fmaf(ww[j], bb[i], acc[j][i]);
        }
        __syncthreads();
    }

#pragma unroll
    for (int j = 0; j < 4; ++j) {
        int col = col0 + (tx << 2) + j;
        float bias = (col < H4) ? (bihF[col] + bhhF[col])
                                : (bihR[col - H4] + bhhR[col - H4]);
        float4 v = make_float4(acc[j][0] + bias, acc[j][1] + bias,
                               acc[j][2] + bias, acc[j][3] + bias);
        *reinterpret_cast<float4*>(&d_Xg[((size_t)s * Gsz + col) * Bsz + (ty << 2)]) = v;
    }
}

// =================================================================================
// Phase B: persistent kernel, 128 blocks x 256 threads, 256 sequential steps.
// Block blk: cell = blk>>6, hidden units [j0, j0+16) (x4 gates = 64 g-columns).
// Step: g-tile GEMM (T @ Whh_slice^T + Xg) -> gates -> h ; barrier ;
//       blocks 0..63: attention + softmax + items + outer product -> T, outputs ;
//       barrier.
// =================================================================================
__global__ void __launch_bounds__(256) phaseB_kernel(
    const float* __restrict__ WhhF, const float* __restrict__ WhhR,
    const float* __restrict__ WaFw, const float* __restrict__ WaFb,
    const float* __restrict__ WaRw, const float* __restrict__ WaRb,
    const float* __restrict__ Fw,   const float* __restrict__ Fb,
    const float* __restrict__ Rw,   const float* __restrict__ Rb,
    float* __restrict__ out)
{
    const int tid  = threadIdx.x;
    const int blk  = blockIdx.x;
    const int cell = blk >> 6;
    const int j0   = (blk & 63) << 4;
    const float* Whh = cell ? WhhR : WhhF;

    __shared__ float Ts[16][68];     // [kk][b]
    __shared__ float Ws[16][68];     // [kk][c]
    __shared__ float gs[64][65];     // [b][c]   c = gate*16 + u
    __shared__ float hsh[2 * Hsz];   // hF | hR for one batch
    __shared__ float lg[256];        // logits / attention weights (200 used)
    __shared__ float items[64];      // itemF[32] | itemR[32]
    __shared__ unsigned s_gen;

    const int tx = tid & 15, ty = tid >> 4;
    const int lb = tid >> 2, lk = (tid & 3) << 2;

    // W row this thread streams (fixed across steps)
    const int   wgate = lb >> 4, wu = lb & 15;
    const float* wrow = Whh + (size_t)(wgate * Hsz + j0 + wu) * Hsz;

    // epilogue mapping: (unit eu, 4 batches eb4*4+i); cell state in registers
    const int eu  = tid & 15;
    const int eb4 = tid >> 4;
    float cst[4] = {0.f, 0.f, 0.f, 0.f};

    // init shared hidden T = 0 (L2-visible for __ldcg readers)
    if (blk < Bsz) {
        for (int j = tid; j < Hsz; j += 256) __stcg(&d_T[blk * Hsz + j], 0.f);
    }
    if (tid == 0) s_gen = atomicAdd(&g_gen, 0u);
    __syncthreads();
    unsigned gen = s_gen;
    gridbar(gen);

    float* outAF = out + (size_t)Bsz * Ssz * Hsz;
    float* outAR = outAF + (size_t)Bsz * Ssz * NS;

    for (int s = 0; s < Ssz; ++s) {
        // ---- prefetch this block's Xg slice (batches ty*4.., cols tx*4..) ----
        float4 xgv[4];
#pragma unroll
        for (int j = 0; j < 4; ++j) {
            int c = (tx << 2) + j;
            int gate = c >> 4, u = c & 15;
            size_t grow = (size_t)cell * H4 + (size_t)gate * Hsz + j0 + u;
            xgv[j] = *reinterpret_cast<const float4*>(
                &d_Xg[((size_t)s * Gsz + grow) * Bsz + (ty << 2)]);
        }

        // ---- GEMM: acc[c][b] = T[b,:] . Whh_row(c)  (K=1024, chunks of 16) ----
        float acc[4][4];
#pragma unroll
        for (int j = 0; j < 4; ++j)
#pragma unroll
            for (int i = 0; i < 4; ++i) acc[j][i] = 0.f;

        float4 tA = __ldcg(reinterpret_cast<const float4*>(&d_T[lb * Hsz + lk]));
        float4 tW = __ldg (reinterpret_cast<const float4*>(&wrow[lk]));
        for (int k0 = 0; k0 < Hsz; k0 += 16) {
            Ts[lk+0][lb] = tA.x; Ts[lk+1][lb] = tA.y; Ts[lk+2][lb] = tA.z; Ts[lk+3][lb] = tA.w;
            Ws[lk+0][lb] = tW.x; Ws[lk+1][lb] = tW.y; Ws[lk+2][lb] = tW.z; Ws[lk+3][lb] = tW.w;
            __syncthreads();
            if (k0 + 16 < Hsz) {
                tA = __ldcg(reinterpret_cast<const float4*>(&d_T[lb * Hsz + k0 + 16 + lk]));
                tW = __ldg (reinterpret_cast<const float4*>(&wrow[k0 + 16 + lk]));
            }
#pragma unroll
            for (int kk = 0; kk < 16; ++kk) {
                float4 bv = *reinterpret_cast<const float4*>(&Ts[kk][ty << 2]);
                float4 wv = *reinterpret_cast<const float4*>(&Ws[kk][tx << 2]);
                const float bb[4] = {bv.x, bv.y, bv.z, bv.w};
                const float ww[4] = {wv.x, wv.y, wv.z, wv.w};
#pragma unroll
                for (int j = 0; j < 4; ++j)
#pragma unroll
                    for (int i = 0; i < 4; ++i) acc[j][i] = fmaf(ww[j], bb[i], acc[j][i]);
            }
            __syncthreads();
        }

        // ---- g = acc + Xg  -> shared, then gates ----
#pragma unroll
        for (int j = 0; j < 4; ++j) {
            const float* xg = reinterpret_cast<const float*>(&xgv[j]);
#pragma unroll
            for (int i = 0; i < 4; ++i)
                gs[(ty << 2) + i][(tx << 2) + j] = acc[j][i] + xg[i];
        }
        __syncthreads();

#pragma unroll
        for (int i = 0; i < 4; ++i) {
            int b = (eb4 << 2) + i;
            float iv = gs[b][eu      ];
            float fv = gs[b][16 + eu ];
            float gv = gs[b][32 + eu ];
            float ov = gs[b][48 + eu ];
            float si = 1.f / (1.f + __expf(-iv));
            float sf = 1.f / (1.f + __expf(-fv));
            float so = 1.f / (1.f + __expf(-ov));
            float c2 = sf * cst[i] + si * tanhf(gv);
            cst[i] = c2;
            float h = so * tanhf(c2);
            __stcg(&d_Hbuf[((size_t)cell * Bsz + b) * Hsz + j0 + eu], h);
        }

        gridbar(gen);   // h complete

        // ---- attention + output: block b (< 64) handles batch b ----
        if (blk < Bsz) {
            const int b = blk;
            for (int i = tid; i < 2 * Hsz; i += 256) {
                int c2 = i >> 10;
                int k  = i & (Hsz - 1);
                hsh[i] = __ldcg(&d_Hbuf[((size_t)c2 * Bsz + b) * Hsz + k]);
            }
            __syncthreads();

            const int warp = tid >> 5, lane = tid & 31;
            for (int r = warp; r < NS + NR; r += 8) {
                const float* wr; const float* hh; float bias;
                if (r < NS) { wr = WaFw + (size_t)r * Hsz;        hh = hsh;       bias = WaFb[r]; }
                else        { wr = WaRw + (size_t)(r - NS) * Hsz; hh = hsh + Hsz; bias = WaRb[r - NS]; }
                float sum = 0.f;
                for (int k = lane; k < Hsz; k += 32) sum = fmaf(__ldg(&wr[k]), hh[k], sum);
#pragma unroll
                for (int off = 16; off; off >>= 1) sum += __shfl_down_sync(0xffffffffu, sum, off);
                if (lane == 0) lg[r] = sum + bias;
            }
            __syncthreads();

            // softmax: warp0 -> F(150), warp1 -> R(50); writes aF/aR outputs too
            if (warp == 0) {
                float m = -1e30f;
                for (int n = lane; n < NS; n += 32) m = fmaxf(m, lg[n]);
#pragma unroll
                for (int off = 16; off; off >>= 1) m = fmaxf(m, __shfl_xor_sync(0xffffffffu, m, off));
                float ssum = 0.f;
                for (int n = lane; n < NS; n += 32) { float e = __expf(lg[n] - m); lg[n] = e; ssum += e; }
#pragma unroll
                for (int off = 16; off; off >>= 1) ssum += __shfl_xor_sync(0xffffffffu, ssum, off);
                float inv = 1.f / ssum;
                for (int n = lane; n < NS; n += 32) {
                    float a = lg[n] * inv; lg[n] = a;
                    outAF[((size_t)b * Ssz + s) * NS + n] = a;
                }
            } else if (warp == 1) {
                float m = -1e30f;
                for (int n = lane; n < NR; n += 32) m = fmaxf(m, lg[NS + n]);
#pragma unroll
                for (int off = 16; off; off >>= 1) m = fmaxf(m, __shfl_xor_sync(0xffffffffu, m, off));
                float ssum = 0.f;
                for (int n = lane; n < NR; n += 32) { float e = __expf(lg[NS + n] - m); lg[NS + n] = e; ssum += e; }
#pragma unroll
                for (int off = 16; off; off >>= 1) ssum += __shfl_xor_sync(0xffffffffu, ssum, off);
                float inv = 1.f / ssum;
                for (int n = lane; n < NR; n += 32) {
                    float a = lg[NS + n] * inv; lg[NS + n] = a;
                    outAR[((size_t)b * Ssz + s) * NR + n] = a;
                }
            }
            __syncthreads();

            // items: itemF[d] = aF . Fw[d,:] + Fb[d] ; itemR likewise
            if (tid < 32) {
                float sum = Fb[tid];
                for (int n = 0; n < NS; ++n) sum = fmaf(lg[n], __ldg(&Fw[tid * NS + n]), sum);
                items[tid] = sum;
            } else if (tid < 64) {
                int d = tid - 32;
                float sum = Rb[d];
                for (int n = 0; n < NR; ++n) sum = fmaf(lg[NS + n], __ldg(&Rw[d * NR + n]), sum);
                items[32 + d] = sum;
            }
            __syncthreads();

            // T[b, ds*32+dr] = itemF[ds]*itemR[dr]; also the main output
            for (int j = tid; j < Hsz; j += 256) {
                float v = items[j >> 5] * items[32 + (j & 31)];
                __stcg(&d_T[b * Hsz + j], v);
                out[((size_t)b * Ssz + s) * Hsz + j] = v;
            }
        }

        gridbar(gen);   // T complete for next step
    }
}

// =================================================================================
extern "C" void kernel_launch(void* const* d_in, const int* in_sizes, int n_in,
                              void* d_out, int out_size) {
    (void)in_sizes; (void)n_in; (void)out_size;
    const float* x    = (const float*)d_in[0];
    const float* WihF = (const float*)d_in[1];
    const float* WhhF = (const float*)d_in[2];
    const float* bihF = (const float*)d_in[3];
    const float* bhhF = (const float*)d_in[4];
    const float* WihR = (const float*)d_in[5];
    const float* WhhR = (const float*)d_in[6];
    const float* bihR = (const float*)d_in[7];
    const float* bhhR = (const float*)d_in[8];
    const float* WaFw = (const float*)d_in[9];
    const float* WaFb = (const float*)d_in[10];
    const float* WaRw = (const float*)d_in[11];
    const float* WaRb = (const float*)d_in[12];
    const float* Fw   = (const float*)d_in[13];
    const float* Fb   = (const float*)d_in[14];
    const float* Rw   = (const float*)d_in[15];
    const float* Rb   = (const float*)d_in[16];
    float* out = (float*)d_out;

    phaseA_kernel<<<dim3(128, 256), 256>>>(x, WihF, WihR, bihF, bhhF, bihR, bhhR);
    phaseB_kernel<<<NBLK, 256>>>(WhhF, WhhR, WaFw, WaFb, WaRw, WaRb, Fw, Fb, Rw, Rb, out);
}